// round 2
// baseline (speedup 1.0000x reference)
#include <cuda_runtime.h>
#include <cuda_pipeline.h>
#include <mma.h>
#include <math.h>

using namespace nvcuda;

#define BB   32
#define NN   1024
#define CIN  2
#define HH   32
#define SS   2
#define CP   48      // padded channel count (34 real)
#define NF   170     // total features per node
#define BM   128     // hop row tile
#define BK   64      // hop k chunk
#define LDA  72      // BK + 8 pad (floats)
#define NCHUNK (NN / BK)

// dynamic smem layout (per buffer): A tile BM*LDA floats, X tile BK*CP floats
#define SA_ELT (BM * LDA)          // 9216 floats = 36864 B
#define SX_ELT (BK * CP)           // 3072 floats = 12288 B
#define SMEM_HOP_BYTES (2 * (SA_ELT + SX_ELT) * 4)   // 98304 B

// ---------------- scratch (device globals; no allocs allowed) ----------------
__device__ alignas(16) float g_X0[BB * NN * CP];        // [b][n][48]
__device__ alignas(16) float g_Y1[BB * SS * NN * CP];   // [b][s][n][48]
__device__ alignas(16) float g_Y2[BB * SS * NN * CP];
__device__ alignas(16) float g_X1[BB * NN * CP];
__device__ alignas(16) float g_Z1[BB * SS * NN * CP];
__device__ alignas(16) float g_Z2[BB * SS * NN * CP];
__device__ alignas(16) float g_U [BB * NN * HH];

__device__ __forceinline__ float* buf_ptr(int sel) {
    switch (sel) {
        case 0:  return g_X0;
        case 1:  return g_Y1;
        case 2:  return g_Y2;
        case 3:  return g_X1;
        case 4:  return g_Z1;
        default: return g_Z2;
    }
}

// ---------------- pack X0 = [inputs | states | 0pad] ----------------
__global__ void pack_x0_kernel(const float* __restrict__ inputs,
                               const float* __restrict__ states) {
    int idx = blockIdx.x * blockDim.x + threadIdx.x;
    if (idx >= BB * NN * CP) return;
    int c  = idx % CP;
    int bn = idx / CP;
    float v = 0.0f;
    if (c < CIN)            v = inputs[bn * CIN + c];
    else if (c < CIN + HH)  v = states[bn * HH + (c - CIN)];
    g_X0[idx] = v;
}

// ---------------- hop: Y[bs] = A[bs] @ X   (tf32 WMMA, cp.async 2-stage) ----
// grid (NN/BM, BB*SS), 256 threads. x_per_bs: X indexed by bs (1) or by b (0).
__device__ __forceinline__ void hop_load_chunk_async(
    float* sA, float* sX, const float* __restrict__ Ag,
    const float* __restrict__ Xg, int tid) {
    // A stripe: 128 rows x 64 cols = 2048 float4 -> 8 per thread
#pragma unroll
    for (int i = 0; i < 8; i++) {
        int idx = tid + i * 256;
        int r   = idx >> 4;            // 0..127
        int c4  = idx & 15;            // 16 float4 per row
        __pipeline_memcpy_async(&sA[r * LDA + c4 * 4],
                                Ag + (size_t)r * NN + c4 * 4, 16);
    }
    // X tile: 64 rows x 48 cols = 768 float4 -> 3 per thread
#pragma unroll
    for (int i = 0; i < 3; i++) {
        int idx = tid + i * 256;
        int r   = idx / 12;
        int c4  = idx % 12;
        __pipeline_memcpy_async(&sX[r * CP + c4 * 4],
                                Xg + r * CP + c4 * 4, 16);
    }
}

__global__ __launch_bounds__(256) void hop_kernel(
    const float* __restrict__ supports, int src_sel, int dst_sel, int x_per_bs) {
    extern __shared__ float smem[];
    float* sA[2] = { smem,                    smem + SA_ELT };
    float* sX[2] = { smem + 2 * SA_ELT,       smem + 2 * SA_ELT + SX_ELT };

    const int tid = threadIdx.x;
    const int wid = tid >> 5;
    const int bs  = blockIdx.y;
    const int b   = bs >> 1;

    const float* A = supports + (size_t)bs * NN * NN;
    const float* X = buf_ptr(src_sel) + (size_t)(x_per_bs ? bs : b) * NN * CP;
    float*       Y = buf_ptr(dst_sel) + (size_t)bs * NN * CP;
    const int row0 = blockIdx.x * BM;
    const float* Abase = A + (size_t)row0 * NN;

    wmma::fragment<wmma::accumulator, 16, 16, 8, float> acc[3];
#pragma unroll
    for (int j = 0; j < 3; j++) wmma::fill_fragment(acc[j], 0.0f);

    // prologue: chunk 0 into buffer 0
    hop_load_chunk_async(sA[0], sX[0], Abase, X, tid);
    __pipeline_commit();

    for (int chunk = 0; chunk < NCHUNK; chunk++) {
        const int buf = chunk & 1;
        if (chunk + 1 < NCHUNK) {
            const int k1 = (chunk + 1) * BK;
            hop_load_chunk_async(sA[buf ^ 1], sX[buf ^ 1],
                                 Abase + k1, X + (size_t)k1 * CP, tid);
            __pipeline_commit();
            __pipeline_wait_prior(1);
        } else {
            __pipeline_wait_prior(0);
        }
        __syncthreads();

        const float* cA = sA[buf];
        const float* cX = sX[buf];
#pragma unroll
        for (int kk = 0; kk < BK; kk += 8) {
            wmma::fragment<wmma::matrix_a, 16, 16, 8, wmma::precision::tf32, wmma::row_major> af;
            wmma::load_matrix_sync(af, &cA[(wid * 16) * LDA + kk], LDA);
#pragma unroll
            for (int t = 0; t < af.num_elements; t++)
                af.x[t] = wmma::__float_to_tf32(af.x[t]);
#pragma unroll
            for (int j = 0; j < 3; j++) {
                wmma::fragment<wmma::matrix_b, 16, 16, 8, wmma::precision::tf32, wmma::row_major> bf;
                wmma::load_matrix_sync(bf, &cX[kk * CP + j * 16], CP);
#pragma unroll
                for (int t = 0; t < bf.num_elements; t++)
                    bf.x[t] = wmma::__float_to_tf32(bf.x[t]);
                wmma::mma_sync(acc[j], af, bf, acc[j]);
            }
        }
        __syncthreads();
    }

#pragma unroll
    for (int j = 0; j < 3; j++)
        wmma::store_matrix_sync(Y + (size_t)(row0 + wid * 16) * CP + j * 16,
                                acc[j], CP, wmma::mem_row_major);
}

// ---------------- gates: r,u = sigmoid(F @ W_ru + b); build X1, store U ----
// grid BB*NN/64 CTAs, 256 threads; 64 rows/CTA in 8 groups of 8 rows.
__global__ __launch_bounds__(256) void gates_kernel(
    const float* __restrict__ inputs, const float* __restrict__ states,
    const float* __restrict__ W_ru, const float* __restrict__ b_ru) {
    __shared__ float sW[NF * 64];   // 43520 B
    __shared__ float sF[8 * NF];    //  5440 B

    const int tid = threadIdx.x;
    for (int i = tid; i < NF * 64; i += 256) sW[i] = W_ru[i];

    const int o  = tid & 63;
    const int rq = tid >> 6;        // 0..3
    const float bias = b_ru[o];
    const int rowBase = blockIdx.x * 64;

    for (int g = 0; g < 8; g++) {
        for (int i = tid; i < 8 * NF; i += 256) {
            int r = i / NF, f = i % NF;
            int R = rowBase + g * 8 + r;
            int bb = R >> 10, n = R & 1023;
            float v;
            if (f < 34)       v = g_X0[(size_t)R * CP + f];
            else if (f < 68)  v = g_Y1[((size_t)(bb * SS) * NN + n) * CP + (f - 34)];
            else if (f < 102) v = g_Y2[((size_t)(bb * SS) * NN + n) * CP + (f - 68)];
            else if (f < 136) v = g_Y1[((size_t)(bb * SS + 1) * NN + n) * CP + (f - 102)];
            else              v = g_Y2[((size_t)(bb * SS + 1) * NN + n) * CP + (f - 136)];
            sF[i] = v;
        }
        __syncthreads();

        float a0 = bias, a1 = bias;
        const float* f0 = &sF[rq * NF];
        const float* f1 = &sF[(rq + 4) * NF];
#pragma unroll 10
        for (int f = 0; f < NF; f++) {
            float w = sW[f * 64 + o];
            a0 += f0[f] * w;
            a1 += f1[f] * w;
        }

#pragma unroll
        for (int t = 0; t < 2; t++) {
            float acc = t ? a1 : a0;
            int R = rowBase + g * 8 + rq + t * 4;
            float sig = 1.0f / (1.0f + expf(-acc));
            size_t xr = (size_t)R * CP;
            if (o < CIN) g_X1[xr + o] = inputs[R * CIN + o];
            if (o < HH) {
                g_X1[xr + CIN + o] = sig * states[(size_t)R * HH + o];  // r-gate
            } else {
                g_U[(size_t)R * HH + (o - HH)] = sig;                   // u-gate
                int zc = o + 2;                                          // 34..47 pad
                if (zc < CP) g_X1[xr + zc] = 0.0f;
            }
        }
        __syncthreads();
    }
}

// ---------------- final: c = tanh(F @ W_c + b); out = u*st + (1-u)*c -------
__global__ __launch_bounds__(256) void final_kernel(
    const float* __restrict__ states, const float* __restrict__ W_c,
    const float* __restrict__ b_c, float* __restrict__ out, int out_size) {
    __shared__ float sW[NF * 32];   // 21760 B
    __shared__ float sF[16 * NF];   // 10880 B

    const int tid = threadIdx.x;
    for (int i = tid; i < NF * 32; i += 256) sW[i] = W_c[i];

    const int o  = tid & 31;
    const int rq = tid >> 5;        // 0..7
    const float bias = b_c[o];
    const int rowBase = blockIdx.x * 64;
    const int total = BB * NN * HH;

    for (int g = 0; g < 4; g++) {
        for (int i = tid; i < 16 * NF; i += 256) {
            int r = i / NF, f = i % NF;
            int R = rowBase + g * 16 + r;
            int bb = R >> 10, n = R & 1023;
            float v;
            if (f < 34)       v = g_X1[(size_t)R * CP + f];
            else if (f < 68)  v = g_Z1[((size_t)(bb * SS) * NN + n) * CP + (f - 34)];
            else if (f < 102) v = g_Z2[((size_t)(bb * SS) * NN + n) * CP + (f - 68)];
            else if (f < 136) v = g_Z1[((size_t)(bb * SS + 1) * NN + n) * CP + (f - 102)];
            else              v = g_Z2[((size_t)(bb * SS + 1) * NN + n) * CP + (f - 136)];
            sF[i] = v;
        }
        __syncthreads();

        float a0 = bias, a1 = bias;
        const float* f0 = &sF[rq * NF];
        const float* f1 = &sF[(rq + 8) * NF];
#pragma unroll 10
        for (int f = 0; f < NF; f++) {
            float w = sW[f * 32 + o];
            a0 += f0[f] * w;
            a1 += f1[f] * w;
        }

#pragma unroll
        for (int t = 0; t < 2; t++) {
            float acc = t ? a1 : a0;
            int R = rowBase + g * 16 + rq + t * 8;
            float c  = tanhf(acc);
            float u  = g_U[(size_t)R * HH + o];
            float st = states[(size_t)R * HH + o];
            float v  = u * st + (1.0f - u) * c;
            out[(size_t)R * HH + o] = v;
            if (out_size >= 2 * total)
                out[(size_t)total + (size_t)R * HH + o] = v;   // (outputs, outputs)
        }
        __syncthreads();
    }
}

// ---------------- launch ----------------
extern "C" void kernel_launch(void* const* d_in, const int* in_sizes, int n_in,
                              void* d_out, int out_size) {
    const float* inputs   = (const float*)d_in[0];   // (32,1024,2)
    const float* supports = (const float*)d_in[1];   // (32,2,1024,1024)
    const float* states   = (const float*)d_in[2];   // (32,1024,32)
    const float* W_ru     = (const float*)d_in[3];   // (170,64)
    const float* b_ru     = (const float*)d_in[4];   // (64)
    const float* W_c      = (const float*)d_in[5];   // (170,32)
    const float* b_c      = (const float*)d_in[6];   // (32)
    float* out = (float*)d_out;

    cudaFuncSetAttribute(hop_kernel,
                         cudaFuncAttributeMaxDynamicSharedMemorySize,
                         SMEM_HOP_BYTES);

    pack_x0_kernel<<<(BB * NN * CP) / 256, 256>>>(inputs, states);

    dim3 hg(NN / BM, BB * SS);
    hop_kernel<<<hg, 256, SMEM_HOP_BYTES>>>(supports, 0, 1, 0);   // Y1 = A @ X0
    hop_kernel<<<hg, 256, SMEM_HOP_BYTES>>>(supports, 1, 2, 1);   // Y2 = A @ Y1

    gates_kernel<<<(BB * NN) / 64, 256>>>(inputs, states, W_ru, b_ru);

    hop_kernel<<<hg, 256, SMEM_HOP_BYTES>>>(supports, 3, 4, 0);   // Z1 = A @ X1
    hop_kernel<<<hg, 256, SMEM_HOP_BYTES>>>(supports, 4, 5, 1);   // Z2 = A @ Z1

    final_kernel<<<(BB * NN) / 64, 256>>>(states, W_c, b_c, out, out_size);
}

// round 3
// speedup vs baseline: 1.0399x; 1.0399x over previous
#include <cuda_runtime.h>
#include <cuda_pipeline.h>
#include <mma.h>
#include <math.h>

using namespace nvcuda;

#define BB   32
#define NN   1024
#define CIN  2
#define HH   32
#define SS   2
#define CP   48      // padded channel count (34 real) for X buffers
#define FP   192     // feature-buffer stride: 4 slots x 48
#define KTOT 240     // gates/final GEMM K: 5 segments x 48
#define BM   128     // hop row tile
#define BK   64      // hop k chunk
#define LDA  72      // BK + 8 pad (floats)
#define NCHUNK (NN / BK)

// hop dynamic smem: double-buffered A tile + X tile
#define SA_ELT (BM * LDA)          // 9216 floats
#define SX_ELT (BK * CP)           // 3072 floats
#define SMEM_HOP_BYTES (2 * (SA_ELT + SX_ELT) * 4)   // 98304 B

// gates smem: W(240x64) + max(F tile 128x48, Out 128x64)
#define SMEM_GATES_BYTES ((KTOT * 64 + 128 * 64) * 4)   // 94208 B
// final smem: W(240x32) + max(F tile 128x48, Out 128x32)
#define SMEM_FINAL_BYTES ((KTOT * 32 + 128 * 48) * 4)   // 55296 B

// ---------------- scratch (device globals; no allocs allowed) ----------------
__device__ alignas(16) float g_X0[BB * NN * CP];        // [b*n][48]
__device__ alignas(16) float g_X1[BB * NN * CP];
__device__ alignas(16) float g_F1[BB * NN * FP];        // conv1 hop outputs, 4 slots
__device__ alignas(16) float g_F2[BB * NN * FP];        // conv2 hop outputs
__device__ alignas(16) float g_U [BB * NN * HH];

// ---------------- pack X0 = [inputs | states | 0pad] ----------------
__global__ void pack_x0_kernel(const float* __restrict__ inputs,
                               const float* __restrict__ states) {
    int idx = blockIdx.x * blockDim.x + threadIdx.x;
    if (idx >= BB * NN * CP) return;
    int c  = idx % CP;
    int bn = idx / CP;
    float v = 0.0f;
    if (c < CIN)            v = inputs[bn * CIN + c];
    else if (c < CIN + HH)  v = states[bn * HH + (c - CIN)];
    g_X0[idx] = v;
}

// ---------------- hop: Y = A @ X   (tf32 WMMA, cp.async 2-stage) ------------
// mode: 0 Y1=A@X0 -> F1 slot s*2 ; 1 Y2=A@Y1 -> F1 slot s*2+1
//       2 Z1=A@X1 -> F2 slot s*2 ; 3 Z2=A@Z1 -> F2 slot s*2+1
__device__ __forceinline__ void hop_load_chunk_async(
    float* sA, float* sX, const float* __restrict__ Ag,
    const float* __restrict__ Xg, int xs, int tid) {
#pragma unroll
    for (int i = 0; i < 8; i++) {              // A: 128x64 = 2048 float4
        int idx = tid + i * 256;
        int r   = idx >> 4;
        int c4  = idx & 15;
        __pipeline_memcpy_async(&sA[r * LDA + c4 * 4],
                                Ag + (size_t)r * NN + c4 * 4, 16);
    }
#pragma unroll
    for (int i = 0; i < 3; i++) {              // X: 64x48 = 768 float4
        int idx = tid + i * 256;
        int r   = idx / 12;
        int c4  = idx % 12;
        __pipeline_memcpy_async(&sX[r * CP + c4 * 4],
                                Xg + (size_t)r * xs + c4 * 4, 16);
    }
}

__global__ __launch_bounds__(256) void hop_kernel(
    const float* __restrict__ supports, int mode) {
    extern __shared__ float smem[];
    float* sA[2] = { smem,              smem + SA_ELT };
    float* sX[2] = { smem + 2 * SA_ELT, smem + 2 * SA_ELT + SX_ELT };

    const int tid = threadIdx.x;
    const int wid = tid >> 5;
    const int bs  = blockIdx.y;
    const int b   = bs >> 1;
    const int s   = bs & 1;

    const float* A = supports + (size_t)bs * NN * NN;
    float* Fbuf = (mode < 2) ? g_F1 : g_F2;
    const float* X;
    int xs;
    if (mode == 0)      { X = g_X0 + (size_t)b * NN * CP; xs = CP; }
    else if (mode == 2) { X = g_X1 + (size_t)b * NN * CP; xs = CP; }
    else                { X = Fbuf + (size_t)b * NN * FP + s * 2 * CP; xs = FP; }
    int slot = s * 2 + ((mode & 1) ? 1 : 0);
    float* Y = Fbuf + (size_t)b * NN * FP + slot * CP;

    const int row0 = blockIdx.x * BM;
    const float* Abase = A + (size_t)row0 * NN;

    wmma::fragment<wmma::accumulator, 16, 16, 8, float> acc[3];
#pragma unroll
    for (int j = 0; j < 3; j++) wmma::fill_fragment(acc[j], 0.0f);

    hop_load_chunk_async(sA[0], sX[0], Abase, X, xs, tid);
    __pipeline_commit();

    for (int chunk = 0; chunk < NCHUNK; chunk++) {
        const int buf = chunk & 1;
        if (chunk + 1 < NCHUNK) {
            const int k1 = (chunk + 1) * BK;
            hop_load_chunk_async(sA[buf ^ 1], sX[buf ^ 1],
                                 Abase + k1, X + (size_t)k1 * xs, xs, tid);
            __pipeline_commit();
            __pipeline_wait_prior(1);
        } else {
            __pipeline_wait_prior(0);
        }
        __syncthreads();

        const float* cA = sA[buf];
        const float* cX = sX[buf];
#pragma unroll
        for (int kk = 0; kk < BK; kk += 8) {
            wmma::fragment<wmma::matrix_a, 16, 16, 8, wmma::precision::tf32, wmma::row_major> af;
            wmma::load_matrix_sync(af, &cA[(wid * 16) * LDA + kk], LDA);
#pragma unroll
            for (int t = 0; t < af.num_elements; t++)
                af.x[t] = wmma::__float_to_tf32(af.x[t]);
#pragma unroll
            for (int j = 0; j < 3; j++) {
                wmma::fragment<wmma::matrix_b, 16, 16, 8, wmma::precision::tf32, wmma::row_major> bf;
                wmma::load_matrix_sync(bf, &cX[kk * CP + j * 16], CP);
#pragma unroll
                for (int t = 0; t < bf.num_elements; t++)
                    bf.x[t] = wmma::__float_to_tf32(bf.x[t]);
                wmma::mma_sync(acc[j], af, bf, acc[j]);
            }
        }
        __syncthreads();
    }

#pragma unroll
    for (int j = 0; j < 3; j++)
        wmma::store_matrix_sync(Y + (size_t)(row0 + wid * 16) * FP + j * 16,
                                acc[j], FP, wmma::mem_row_major);
}

// ---------------- gates: WMMA [128 x 240] @ [240 x 64] + sigmoid epilogue ---
__global__ __launch_bounds__(256) void gates_kernel(
    const float* __restrict__ inputs, const float* __restrict__ states,
    const float* __restrict__ W_ru, const float* __restrict__ b_ru) {
    extern __shared__ float sm[];
    float* sW = sm;                 // 240 x 64 (tf32-rounded)
    float* sF = sm + KTOT * 64;     // F chunk 128x48 / Out 128x64

    const int tid = threadIdx.x;
    const int wid = tid >> 5;
    const int rowBase = blockIdx.x * 128;

    for (int i = tid; i < KTOT * 64; i += 256) {
        int r = i >> 6, o = i & 63;
        int seg = r / CP, c = r % CP;
        float v = (c < 34) ? W_ru[(seg * 34 + c) * 64 + o] : 0.0f;
        sW[i] = wmma::__float_to_tf32(v);
    }

    wmma::fragment<wmma::accumulator, 16, 16, 8, float> acc[4];
#pragma unroll
    for (int j = 0; j < 4; j++) wmma::fill_fragment(acc[j], 0.0f);

    for (int seg = 0; seg < 5; seg++) {
        const float* src;
        int xs;
        if (seg == 0) { src = g_X0 + (size_t)rowBase * CP; xs = CP; }
        else          { src = g_F1 + (size_t)rowBase * FP + (seg - 1) * CP; xs = FP; }
        __syncthreads();
        for (int i = tid; i < 1536; i += 256) {      // 128 rows x 12 float4
            int r = i / 12, c4 = i % 12;
            __pipeline_memcpy_async(&sF[r * CP + c4 * 4],
                                    src + (size_t)r * xs + c4 * 4, 16);
        }
        __pipeline_commit();
        __pipeline_wait_prior(0);
        __syncthreads();

#pragma unroll
        for (int kk = 0; kk < CP; kk += 8) {
            wmma::fragment<wmma::matrix_a, 16, 16, 8, wmma::precision::tf32, wmma::row_major> af;
            wmma::load_matrix_sync(af, &sF[(wid * 16) * CP + kk], CP);
#pragma unroll
            for (int t = 0; t < af.num_elements; t++)
                af.x[t] = wmma::__float_to_tf32(af.x[t]);
#pragma unroll
            for (int j = 0; j < 4; j++) {
                wmma::fragment<wmma::matrix_b, 16, 16, 8, wmma::precision::tf32, wmma::row_major> bf;
                wmma::load_matrix_sync(bf, &sW[(seg * CP + kk) * 64 + j * 16], 64);
                wmma::mma_sync(acc[j], af, bf, acc[j]);
            }
        }
    }

    __syncthreads();
#pragma unroll
    for (int j = 0; j < 4; j++)
        wmma::store_matrix_sync(&sF[(wid * 16) * 64 + j * 16], acc[j], 64,
                                wmma::mem_row_major);
    __syncthreads();

    for (int idx = tid; idx < 128 * 64; idx += 256) {
        int r = idx >> 6, o = idx & 63;
        int R = rowBase + r;
        float v = sF[idx] + b_ru[o];
        float sig = 1.0f / (1.0f + expf(-v));
        if (o < HH) g_X1[(size_t)R * CP + CIN + o] = sig * states[(size_t)R * HH + o];
        else        g_U[(size_t)R * HH + (o - HH)] = sig;
    }
    for (int idx = tid; idx < 128 * 16; idx += 256) {
        int r = idx >> 4, c = idx & 15;
        int R = rowBase + r;
        if (c < 14) g_X1[(size_t)R * CP + 34 + c] = 0.0f;
        else        g_X1[(size_t)R * CP + (c - 14)] = inputs[R * CIN + (c - 14)];
    }
}

// ---------------- final: WMMA [128 x 240] @ [240 x 32] + tanh epilogue ------
__global__ __launch_bounds__(256) void final_kernel(
    const float* __restrict__ states, const float* __restrict__ W_c,
    const float* __restrict__ b_c, float* __restrict__ out, int out_size) {
    extern __shared__ float sm[];
    float* sW = sm;                 // 240 x 32
    float* sF = sm + KTOT * 32;     // F chunk 128x48 / Out 128x32

    const int tid = threadIdx.x;
    const int wid = tid >> 5;
    const int rowBase = blockIdx.x * 128;
    const int total = BB * NN * HH;

    for (int i = tid; i < KTOT * 32; i += 256) {
        int r = i >> 5, o = i & 31;
        int seg = r / CP, c = r % CP;
        float v = (c < 34) ? W_c[(seg * 34 + c) * 32 + o] : 0.0f;
        sW[i] = wmma::__float_to_tf32(v);
    }

    wmma::fragment<wmma::accumulator, 16, 16, 8, float> acc[2];
#pragma unroll
    for (int j = 0; j < 2; j++) wmma::fill_fragment(acc[j], 0.0f);

    for (int seg = 0; seg < 5; seg++) {
        const float* src;
        int xs;
        if (seg == 0) { src = g_X1 + (size_t)rowBase * CP; xs = CP; }
        else          { src = g_F2 + (size_t)rowBase * FP + (seg - 1) * CP; xs = FP; }
        __syncthreads();
        for (int i = tid; i < 1536; i += 256) {
            int r = i / 12, c4 = i % 12;
            __pipeline_memcpy_async(&sF[r * CP + c4 * 4],
                                    src + (size_t)r * xs + c4 * 4, 16);
        }
        __pipeline_commit();
        __pipeline_wait_prior(0);
        __syncthreads();

#pragma unroll
        for (int kk = 0; kk < CP; kk += 8) {
            wmma::fragment<wmma::matrix_a, 16, 16, 8, wmma::precision::tf32, wmma::row_major> af;
            wmma::load_matrix_sync(af, &sF[(wid * 16) * CP + kk], CP);
#pragma unroll
            for (int t = 0; t < af.num_elements; t++)
                af.x[t] = wmma::__float_to_tf32(af.x[t]);
#pragma unroll
            for (int j = 0; j < 2; j++) {
                wmma::fragment<wmma::matrix_b, 16, 16, 8, wmma::precision::tf32, wmma::row_major> bf;
                wmma::load_matrix_sync(bf, &sW[(seg * CP + kk) * 32 + j * 16], 32);
                wmma::mma_sync(acc[j], af, bf, acc[j]);
            }
        }
    }

    __syncthreads();
#pragma unroll
    for (int j = 0; j < 2; j++)
        wmma::store_matrix_sync(&sF[(wid * 16) * 32 + j * 16], acc[j], 32,
                                wmma::mem_row_major);
    __syncthreads();

    for (int idx = tid; idx < 128 * 32; idx += 256) {
        int r = idx >> 5, o = idx & 31;
        int R = rowBase + r;
        float v = sF[idx] + b_c[o];
        float c  = tanhf(v);
        float u  = g_U[(size_t)R * HH + o];
        float st = states[(size_t)R * HH + o];
        float res = u * st + (1.0f - u) * c;
        out[(size_t)R * HH + o] = res;
        if (out_size >= 2 * total)
            out[(size_t)total + (size_t)R * HH + o] = res;
    }
}

// ---------------- launch ----------------
extern "C" void kernel_launch(void* const* d_in, const int* in_sizes, int n_in,
                              void* d_out, int out_size) {
    const float* inputs   = (const float*)d_in[0];   // (32,1024,2)
    const float* supports = (const float*)d_in[1];   // (32,2,1024,1024)
    const float* states   = (const float*)d_in[2];   // (32,1024,32)
    const float* W_ru     = (const float*)d_in[3];   // (170,64)
    const float* b_ru     = (const float*)d_in[4];   // (64)
    const float* W_c      = (const float*)d_in[5];   // (170,32)
    const float* b_c      = (const float*)d_in[6];   // (32)
    float* out = (float*)d_out;

    static bool attr_done = false;
    if (!attr_done) {
        cudaFuncSetAttribute(hop_kernel,
                             cudaFuncAttributeMaxDynamicSharedMemorySize,
                             SMEM_HOP_BYTES);
        cudaFuncSetAttribute(gates_kernel,
                             cudaFuncAttributeMaxDynamicSharedMemorySize,
                             SMEM_GATES_BYTES);
        cudaFuncSetAttribute(final_kernel,
                             cudaFuncAttributeMaxDynamicSharedMemorySize,
                             SMEM_FINAL_BYTES);
        attr_done = true;
    }

    pack_x0_kernel<<<(BB * NN * CP) / 256, 256>>>(inputs, states);

    dim3 hg(NN / BM, BB * SS);
    hop_kernel<<<hg, 256, SMEM_HOP_BYTES>>>(supports, 0);   // Y1
    hop_kernel<<<hg, 256, SMEM_HOP_BYTES>>>(supports, 1);   // Y2

    gates_kernel<<<(BB * NN) / 128, 256, SMEM_GATES_BYTES>>>(inputs, states, W_ru, b_ru);

    hop_kernel<<<hg, 256, SMEM_HOP_BYTES>>>(supports, 2);   // Z1
    hop_kernel<<<hg, 256, SMEM_HOP_BYTES>>>(supports, 3);   // Z2

    final_kernel<<<(BB * NN) / 128, 256, SMEM_FINAL_BYTES>>>(states, W_c, b_c, out, out_size);
}